// round 5
// baseline (speedup 1.0000x reference)
#include <cuda_runtime.h>
#include <cstdint>

// DilatedMask: out = float32( 33x33 sliding max of (x==0) ), separable, binary.
// Single monolithic kernel: each block produces a 256x256 output tile from a
// 288x288 input halo. Output written as float32 (harness promotes uint8).

#define B_   8
#define H_   2048
#define W_   2048
#define R_   16
#define TR   256                 // tile rows
#define TC   256                 // tile cols
#define HR   (TR + 2 * R_)       // 288 halo rows
#define HW   9                   // 288 halo bits per row -> 9 words
#define SBW  11                  // sB row stride: 9 data words + zero pad each side

// Horizontal dilation of word `mid` by +-16 bits, neighbors lo (lower x) / hi.
__device__ __forceinline__ uint32_t hdil(uint32_t lo, uint32_t mid, uint32_t hi)
{
    // sources at lower x (offsets 0..16)
    const uint64_t a = ((uint64_t)mid << 32) | lo;
    uint64_t u = a | (a << 1);
    u |= u << 2;  u |= u << 4;  u |= u << 8;   // offsets 0..15
    u |= a << 16;                              // offset 16

    // sources at higher x (offsets 0..16)
    const uint64_t bcat = ((uint64_t)hi << 32) | mid;
    uint64_t d = bcat | (bcat >> 1);
    d |= d >> 2;  d |= d >> 4;  d |= d >> 8;
    d |= bcat >> 16;

    return (uint32_t)(u >> 32) | (uint32_t)d;
}

__global__ __launch_bounds__(256) void dilate_kernel(
    const float* __restrict__ x, float* __restrict__ out)
{
    __shared__ uint32_t sA[HR * HW];    // packed halo bits      (10.1 KB)
    __shared__ uint32_t sB[TR * SBW];   // vertically dilated     (11.0 KB)

    const int b    = blockIdx.z;
    const int y0   = blockIdx.y * TR;
    const int x0   = blockIdx.x * TC;
    const int tid  = threadIdx.x;
    const int lane = tid & 31;
    const int wp   = tid >> 5;

    const float* img = x + (size_t)b * H_ * W_;

    // ---- Phase 1: ballot-bitpack (x==0) over the 288x288 halo into sA ----
    const int base = wp * (HR * HW / 8);            // 324 words per warp
    for (int k = 0; k < HR * HW / 8; k += 4) {      // 4-way MLP batch
        float v[4]; bool ok[4]; int mm[4];
        #pragma unroll
        for (int j = 0; j < 4; ++j) {
            const int m  = base + k + j;
            mm[j] = m;
            const int r  = m / HW;
            const int w  = m - r * HW;
            const int y  = y0 - R_ + r;
            const int cx = x0 - R_ + w * 32 + lane;
            const int yc = min(max(y, 0), H_ - 1);  // always in-bounds address
            const int xc = min(max(cx, 0), W_ - 1);
            v[j]  = img[(size_t)yc * W_ + xc];
            ok[j] = ((unsigned)y < (unsigned)H_) && ((unsigned)cx < (unsigned)W_);
        }
        #pragma unroll
        for (int j = 0; j < 4; ++j) {
            const unsigned bits =
                __ballot_sync(0xffffffffu, ok[j] && (v[j] == 0.0f));
            if (lane == 0) sA[mm[j]] = bits;
        }
    }
    __syncthreads();

    // ---- Phase 2: vertical OR over 33 rows ----
    for (int t = tid; t < TR * HW; t += 256) {      // t = r*9 + w
        const int r = t / HW;
        const int w = t - r * HW;
        uint32_t acc = 0u;
        #pragma unroll
        for (int d = 0; d <= 2 * R_; ++d)
            acc |= sA[t + d * HW];
        sB[r * SBW + 1 + w] = acc;
    }
    for (int r = tid; r < TR; r += 256) {           // zero side pads
        sB[r * SBW]      = 0u;
        sB[r * SBW + 10] = 0u;
    }
    __syncthreads();

    // ---- Phase 3: horizontal +-16-bit dilation, expand bits -> float32 ----
    for (int t = tid; t < TR * 8; t += 256) {       // t = r*8 + j
        const int r = t >> 3;
        const int j = t & 7;
        const uint32_t* row = &sB[r * SBW + j];
        const uint32_t w0 = row[0], w1 = row[1], w2 = row[2], w3 = row[3];

        const uint32_t D0 = hdil(w0, w1, w2);       // dilated halo word j
        const uint32_t D1 = hdil(w1, w2, w3);       // dilated halo word j+1
        // output word j = halo bits 16+32j .. 47+32j
        const uint32_t rb = (D0 >> 16) | (D1 << 16);

        float4* o = (float4*)(out + ((size_t)(b * H_ + y0 + r)) * W_
                                  + (size_t)x0 + (size_t)j * 32);
        #pragma unroll
        for (int kk = 0; kk < 8; ++kk) {
            o[kk] = make_float4(
                (rb >> (4 * kk + 0)) & 1u ? 1.0f : 0.0f,
                (rb >> (4 * kk + 1)) & 1u ? 1.0f : 0.0f,
                (rb >> (4 * kk + 2)) & 1u ? 1.0f : 0.0f,
                (rb >> (4 * kk + 3)) & 1u ? 1.0f : 0.0f);
        }
    }
}

// ---------------------------------------------------------------------------
extern "C" void kernel_launch(void* const* d_in, const int* in_sizes, int n_in,
                              void* d_out, int out_size)
{
    const float* x = (const float*)d_in[0];
    float* out = (float*)d_out;

    dim3 grid(W_ / TC, H_ / TR, B_);    // (8, 8, 8) = 512 blocks
    dilate_kernel<<<grid, 256>>>(x, out);
}

// round 6
// speedup vs baseline: 1.3727x; 1.3727x over previous
#include <cuda_runtime.h>
#include <cstdint>

// DilatedMask: out = float32( 33x33 sliding max of (x==0) ), separable, binary.
// Kernel 1: streaming ballot-bitpack of input -> 4 MB packed bits (L2-resident)
// Kernel 2: full-row-width tiles: vertical 33-row OR (smem) + horizontal
//           +-16-bit shift/OR dilation + bit->float expand.

#define B_   8
#define H_   2048
#define W_   2048
#define R_   16
#define WPR  64                       // 32-bit words per image row
#define NW   (B_ * H_ * WPR)          // 1,048,576 packed words
#define TRB  16                       // output rows per block in kernel 2
#define HRB  (TRB + 2 * R_)           // 48 halo rows
#define SBW  66                       // padded row stride for dilated smem

__device__ uint32_t g_pack[NW];       // 4 MB

// ---------------------------------------------------------------------------
// Kernel 1: bitpack. Each warp packs 8 consecutive words (256 pixels).
// ---------------------------------------------------------------------------
__global__ __launch_bounds__(256) void pack_kernel(const float* __restrict__ x)
{
    const int lane = threadIdx.x & 31;
    const int warp = threadIdx.x >> 5;
    const int w0   = (blockIdx.x * 8 + warp) * 8;   // first of 8 words

    float v[8];
    #pragma unroll
    for (int j = 0; j < 8; ++j)
        v[j] = x[(size_t)(w0 + j) * 32 + lane];     // 128B coalesced

    uint32_t bits[8];
    #pragma unroll
    for (int j = 0; j < 8; ++j)
        bits[j] = __ballot_sync(0xffffffffu, v[j] == 0.0f);

    uint32_t myb = bits[0];                         // lane j keeps bits[j]
    #pragma unroll
    for (int j = 1; j < 8; ++j)
        if (lane == j) myb = bits[j];
    if (lane < 8) g_pack[w0 + lane] = myb;
}

// Horizontal dilation of `mid` by +-16 bits; lo = word at lower x, hi = higher x.
__device__ __forceinline__ uint32_t hdil(uint32_t lo, uint32_t mid, uint32_t hi)
{
    const uint64_t a = ((uint64_t)mid << 32) | lo;  // offsets 0..16 from lower x
    uint64_t u = a | (a << 1);
    u |= u << 2;  u |= u << 4;  u |= u << 8;        // 0..15
    u |= a << 16;                                   // 16

    const uint64_t bcat = ((uint64_t)hi << 32) | mid;
    uint64_t d = bcat | (bcat >> 1);
    d |= d >> 2;  d |= d >> 4;  d |= d >> 8;
    d |= bcat >> 16;

    return (uint32_t)(u >> 32) | (uint32_t)d;
}

// ---------------------------------------------------------------------------
// Kernel 2: per block = full 2048-wide stripe of TRB output rows.
// ---------------------------------------------------------------------------
__global__ __launch_bounds__(256) void dilate_kernel(float* __restrict__ out)
{
    __shared__ uint32_t sA[HRB * WPR];   // packed halo rows   (12 KB)
    __shared__ uint32_t sB[TRB * SBW];   // vert-dilated rows  (4.2 KB)

    const int b   = blockIdx.z;
    const int y0  = blockIdx.y * TRB;
    const int tid = threadIdx.x;
    const uint32_t* in = g_pack + (size_t)b * H_ * WPR;

    // load halo rows [y0-16, y0+TRB+16), zero outside image
    for (int t = tid; t < HRB * WPR; t += 256) {
        const int row = t >> 6;
        const int w   = t & 63;
        const int y   = y0 - R_ + row;
        const int yc  = min(max(y, 0), H_ - 1);      // in-bounds address
        uint32_t v = in[(size_t)yc * WPR + w];
        if ((unsigned)y >= (unsigned)H_) v = 0u;
        sA[t] = v;
    }
    __syncthreads();

    // vertical OR over 33 rows
    for (int t = tid; t < TRB * WPR; t += 256) {     // t = r*64 + w
        const int r = t >> 6;
        const int w = t & 63;
        uint32_t acc = 0u;
        #pragma unroll
        for (int d = 0; d <= 2 * R_; ++d)
            acc |= sA[t + d * WPR];                  // conflict-free
        sB[r * SBW + 1 + w] = acc;
    }
    for (int r = tid; r < TRB; r += 256) {           // zero row-end pads
        sB[r * SBW]      = 0u;
        sB[r * SBW + 65] = 0u;
    }
    __syncthreads();

    // horizontal +-16-bit dilation + expand bits -> float32
    for (int t = tid; t < TRB * WPR; t += 256) {     // t = r*64 + j
        const int r = t >> 6;
        const int j = t & 63;
        const uint32_t* row = &sB[r * SBW + j];      // [j, j+2] in 0..65
        const uint32_t rb = hdil(row[0], row[1], row[2]);

        float4* o = (float4*)(out + ((size_t)(b * H_ + y0 + r)) * W_
                                  + (size_t)j * 32);
        #pragma unroll
        for (int kk = 0; kk < 8; ++kk) {
            o[kk] = make_float4(
                (rb >> (4 * kk + 0)) & 1u ? 1.0f : 0.0f,
                (rb >> (4 * kk + 1)) & 1u ? 1.0f : 0.0f,
                (rb >> (4 * kk + 2)) & 1u ? 1.0f : 0.0f,
                (rb >> (4 * kk + 3)) & 1u ? 1.0f : 0.0f);
        }
    }
}

// ---------------------------------------------------------------------------
extern "C" void kernel_launch(void* const* d_in, const int* in_sizes, int n_in,
                              void* d_out, int out_size)
{
    const float* x = (const float*)d_in[0];
    float* out = (float*)d_out;

    pack_kernel<<<NW / 64, 256>>>(x);                // 16384 blocks
    dim3 g2(1, H_ / TRB, B_);                        // (1, 128, 8) = 1024 blocks
    dilate_kernel<<<g2, 256>>>(out);
}